// round 2
// baseline (speedup 1.0000x reference)
#include <cuda_runtime.h>
#include <stdint.h>

// SpatialTransformer_with_disp: trilinear warp, B=2, D=160, H=192, W=224, C=1.
// Output = concat(warped [B*D*H*W], flow [B*D*H*W*3]) as float32.
// Single fused kernel: reads flow once (coalesced float4 via smem), writes both
// the warped volume and the verbatim flow copy.

constexpr int Dd = 160;
constexpr int Hh = 192;
constexpr int Ww = 224;                 // threads per block = one W-row
constexpr int ROW_F = Ww * 3;           // 672 flow floats per row
constexpr int ROW_F4 = ROW_F / 4;       // 168 float4 per row

__device__ __forceinline__ void axis_interp(float loc, float maxl,
                                            int& i0, int& i1, float& wlo) {
    float cl = fminf(fmaxf(loc, 0.0f), maxl);
    float l0 = fminf(fmaxf(floorf(loc), 0.0f), maxl);
    float l1 = fminf(l0 + 1.0f, maxl);
    i0 = (int)l0;
    i1 = (int)l1;
    wlo = l1 - cl;   // neurite convention: low-corner weight = loc1 - clipped_loc
}

__global__ __launch_bounds__(Ww) void warp_fused_kernel(
    const float* __restrict__ vol,    // [B, D, H, W]
    const float* __restrict__ flow,   // [B, D, H, W, 3]
    float* __restrict__ warped,       // [B, D, H, W]        (= out)
    float* __restrict__ flow_copy,    // [B, D, H, W, 3]     (= out + nv), may be null
    int do_copy)
{
    __shared__ float s[ROW_F];

    const int x = threadIdx.x;       // 0..223
    const int y = blockIdx.x;        // 0..191
    const int z = blockIdx.y;        // 0..159
    const int b = blockIdx.z;        // 0..1

    const long row = (long)((b * Dd + z) * Hh + y);   // row index in [B*D*H]
    const long vox = row * Ww + x;
    const long fbase = row * ROW_F;                   // float offset of this row's flow

    // Stage this row's 672 flow floats through smem with coalesced float4 loads;
    // same registers produce the verbatim copy write.
    if (x < ROW_F4) {
        const float4 v = __ldg(((const float4*)(flow + fbase)) + x);
        ((float4*)s)[x] = v;
        if (do_copy) ((float4*)(flow_copy + fbase))[x] = v;
    }
    __syncthreads();

    const float fz = s[3 * x + 0];
    const float fy = s[3 * x + 1];
    const float fx = s[3 * x + 2];

    int i0z, i1z, i0y, i1y, i0x, i1x;
    float wz0, wy0, wx0;
    axis_interp((float)z + fz, (float)(Dd - 1), i0z, i1z, wz0);
    axis_interp((float)y + fy, (float)(Hh - 1), i0y, i1y, wy0);
    axis_interp((float)x + fx, (float)(Ww - 1), i0x, i1x, wx0);
    const float wz1 = 1.0f - wz0;
    const float wy1 = 1.0f - wy0;
    const float wx1 = 1.0f - wx0;

    const float* vb = vol + (long)b * Dd * Hh * Ww;

    const long r00 = ((long)i0z * Hh + i0y) * Ww;
    const long r01 = ((long)i0z * Hh + i1y) * Ww;
    const long r10 = ((long)i1z * Hh + i0y) * Ww;
    const long r11 = ((long)i1z * Hh + i1y) * Ww;

    // 8 independent gathers -> MLP=8
    const float v000 = __ldg(&vb[r00 + i0x]);
    const float v001 = __ldg(&vb[r00 + i1x]);
    const float v010 = __ldg(&vb[r01 + i0x]);
    const float v011 = __ldg(&vb[r01 + i1x]);
    const float v100 = __ldg(&vb[r10 + i0x]);
    const float v101 = __ldg(&vb[r10 + i1x]);
    const float v110 = __ldg(&vb[r11 + i0x]);
    const float v111 = __ldg(&vb[r11 + i1x]);

    const float c00 = v000 * wx0 + v001 * wx1;
    const float c01 = v010 * wx0 + v011 * wx1;
    const float c10 = v100 * wx0 + v101 * wx1;
    const float c11 = v110 * wx0 + v111 * wx1;

    const float c0 = c00 * wy0 + c01 * wy1;
    const float c1 = c10 * wy0 + c11 * wy1;

    warped[vox] = c0 * wz0 + c1 * wz1;
}

extern "C" void kernel_launch(void* const* d_in, const int* in_sizes, int n_in,
                              void* d_out, int out_size) {
    const float* vol  = (const float*)d_in[0];
    const float* flow = (const float*)d_in[1];
    float* out = (float*)d_out;

    const long nv = (long)in_sizes[0];  // B*D*H*W*C  = 13,762,560
    const long nf = (long)in_sizes[1];  // B*D*H*W*3  = 41,287,680

    const int do_copy = ((long)out_size >= nv + nf) ? 1 : 0;
    float* flow_copy = do_copy ? (out + nv) : out;  // unused when do_copy==0

    dim3 block(Ww, 1, 1);
    dim3 grid(Hh, Dd, 2);
    warp_fused_kernel<<<grid, block>>>(vol, flow, out, flow_copy, do_copy);
}